// round 10
// baseline (speedup 1.0000x reference)
#include <cuda_runtime.h>
#include <math_constants.h>
#include <cstdint>

#define NB 2
#define NQ 2048
#define NKK 2048
#define DMODEL 512
#define NH 8
#define DHEAD 64
#define NF 5
#define LOG2E 1.44269504088896f

#define NLUT 2048
#define DMAX 14.143f
#define LUT_H (DMAX / NLUT)
#define LUT_K (NLUT / DMAX)

// Scratch (allocation-free rule: __device__ globals)
__device__ float g_q[NB*NH*NQ*DHEAD];     // tf32-rounded bits
__device__ float g_k[NB*NH*NKK*DHEAD];    // tf32-rounded bits
__device__ float g_v[NB*NH*NKK*DHEAD];    // tf32-rounded bits
__device__ float g_ctx[NB*NQ*DMODEL];     // fp32
__device__ float g_t[(size_t)NB*NQ*NKK];  // d(q,k) * LUT_K  (head-independent)

__device__ __forceinline__ float ex2f(float x) {
    float y; asm("ex2.approx.ftz.f32 %0, %1;" : "=f"(y) : "f"(x)); return y;
}
__device__ __forceinline__ float rsqrtaf(float x) {
    float y; asm("rsqrt.approx.ftz.f32 %0, %1;" : "=f"(y) : "f"(x)); return y;
}
__device__ __forceinline__ uint32_t f2tf32(float x) {
    uint32_t r; asm("cvt.rna.tf32.f32 %0, %1;" : "=r"(r) : "f"(x)); return r;
}
__device__ __forceinline__ void mma_tf32(float c[4],
    uint32_t a0, uint32_t a1, uint32_t a2, uint32_t a3,
    uint32_t b0, uint32_t b1)
{
    asm volatile(
        "mma.sync.aligned.m16n8k8.row.col.f32.tf32.tf32.f32 "
        "{%0,%1,%2,%3}, {%4,%5,%6,%7}, {%8,%9}, {%0,%1,%2,%3};\n"
        : "+f"(c[0]), "+f"(c[1]), "+f"(c[2]), "+f"(c[3])
        : "r"(a0), "r"(a1), "r"(a2), "r"(a3), "r"(b0), "r"(b1));
}
__device__ __forceinline__ void cp16(void* dst_smem, const void* src) {
    uint32_t d = (uint32_t)__cvta_generic_to_shared(dst_smem);
    asm volatile("cp.async.cg.shared.global [%0], [%1], 16;" :: "r"(d), "l"(src));
}
__device__ __forceinline__ void cp_wait_all() {
    asm volatile("cp.async.commit_group;\n\tcp.async.wait_group 0;" ::: "memory");
}

// ---------------------------------------------------------------------------
// Distance precompute: g_t[b][q][k] = ||qloc - kloc|| * LUT_K  (head-indep)
// ---------------------------------------------------------------------------
__global__ __launch_bounds__(256) void dist_kernel(
    const float* __restrict__ qlocs, const float* __restrict__ klocs)
{
    const int q = blockIdx.x, b = blockIdx.y;
    const float2 ql = *(const float2*)(qlocs + ((size_t)b * NQ + q) * 2);
    const float* kl = klocs + (size_t)b * NKK * 2;
    float* trow = g_t + ((size_t)b * NQ + q) * NKK;
    const int k0 = threadIdx.x * 8;

    float res[8];
    #pragma unroll
    for (int e = 0; e < 4; e++) {
        float4 kk = *(const float4*)(kl + (k0 + 2 * e) * 2);  // 2 klocs
        float dx0 = ql.x - kk.x, dy0 = ql.y - kk.y;
        float dx1 = ql.x - kk.z, dy1 = ql.y - kk.w;
        float d20 = fmaxf(fmaf(dx0, dx0, dy0 * dy0), 1e-24f);
        float d21 = fmaxf(fmaf(dx1, dx1, dy1 * dy1), 1e-24f);
        res[2*e]   = d20 * rsqrtaf(d20) * LUT_K;
        res[2*e+1] = d21 * rsqrtaf(d21) * LUT_K;
    }
    *(float4*)(trow + k0)     = make_float4(res[0], res[1], res[2], res[3]);
    *(float4*)(trow + k0 + 4) = make_float4(res[4], res[5], res[6], res[7]);
}

// ---------------------------------------------------------------------------
// tf32 GEMM body: out = (X[M,512] @ W[512,512] + bias) * scale
// CTA 128x64, 256 threads, double-buffered smem, 1 sync/k-step.
// SPLIT=1: head-split layout + tf32-rounded store. SPLIT=0: plain fp32.
// ---------------------------------------------------------------------------
template<int SPLIT>
__device__ __forceinline__ void gemm_body(
    const float* __restrict__ X, const float* __restrict__ W,
    const float* __restrict__ bias, float* __restrict__ out, float scale)
{
    __shared__ float As[2][128 * 20];  // [m][k16] pad 20
    __shared__ float Bs[2][16 * 72];   // [k][n64] pad 72

    const int tid  = threadIdx.x;
    const int warp = tid >> 5, lane = tid & 31;
    const int grp  = lane >> 2, qd = lane & 3;
    const int bm = blockIdx.y * 128, bn = blockIdx.x * 64;

    const int am = tid >> 2, ac = tid & 3;          // A fill coords
    const int bk = tid >> 4, bc = tid & 15;         // B fill coords

    float C[8][4] = {};
    float4 xr0, xr1, wr;

    // prologue: tile 0
    xr0 = *(const float4*)(X + (size_t)(bm + am) * 512 + ac * 4);
    xr1 = *(const float4*)(X + (size_t)(bm + am + 64) * 512 + ac * 4);
    wr  = *(const float4*)(W + (size_t)bk * 512 + bn + bc * 4);
    {
        uint4 t0 = { f2tf32(xr0.x), f2tf32(xr0.y), f2tf32(xr0.z), f2tf32(xr0.w) };
        uint4 t1 = { f2tf32(xr1.x), f2tf32(xr1.y), f2tf32(xr1.z), f2tf32(xr1.w) };
        uint4 tw = { f2tf32(wr.x),  f2tf32(wr.y),  f2tf32(wr.z),  f2tf32(wr.w)  };
        *(uint4*)&As[0][am * 20 + ac * 4] = t0;
        *(uint4*)&As[0][(am + 64) * 20 + ac * 4] = t1;
        *(uint4*)&Bs[0][bk * 72 + bc * 4] = tw;
    }
    __syncthreads();

    for (int k0 = 0; k0 < 512; k0 += 16) {
        const int cur = (k0 >> 4) & 1;
        const bool hasNext = (k0 + 16 < 512);
        if (hasNext) {
            xr0 = *(const float4*)(X + (size_t)(bm + am) * 512 + k0 + 16 + ac * 4);
            xr1 = *(const float4*)(X + (size_t)(bm + am + 64) * 512 + k0 + 16 + ac * 4);
            wr  = *(const float4*)(W + (size_t)(k0 + 16 + bk) * 512 + bn + bc * 4);
        }

        #pragma unroll
        for (int k8 = 0; k8 < 2; k8++) {
            int kc = k8 * 8 + qd;
            uint32_t a0 = __float_as_uint(As[cur][(warp*16 + grp    ) * 20 + kc    ]);
            uint32_t a1 = __float_as_uint(As[cur][(warp*16 + grp + 8) * 20 + kc    ]);
            uint32_t a2 = __float_as_uint(As[cur][(warp*16 + grp    ) * 20 + kc + 4]);
            uint32_t a3 = __float_as_uint(As[cur][(warp*16 + grp + 8) * 20 + kc + 4]);
            #pragma unroll
            for (int j = 0; j < 8; j++) {
                uint32_t b0 = __float_as_uint(Bs[cur][(k8*8 + qd    ) * 72 + j*8 + grp]);
                uint32_t b1 = __float_as_uint(Bs[cur][(k8*8 + qd + 4) * 72 + j*8 + grp]);
                mma_tf32(C[j], a0, a1, a2, a3, b0, b1);
            }
        }

        if (hasNext) {
            int nxt = cur ^ 1;
            uint4 t0 = { f2tf32(xr0.x), f2tf32(xr0.y), f2tf32(xr0.z), f2tf32(xr0.w) };
            uint4 t1 = { f2tf32(xr1.x), f2tf32(xr1.y), f2tf32(xr1.z), f2tf32(xr1.w) };
            uint4 tw = { f2tf32(wr.x),  f2tf32(wr.y),  f2tf32(wr.z),  f2tf32(wr.w)  };
            *(uint4*)&As[nxt][am * 20 + ac * 4] = t0;
            *(uint4*)&As[nxt][(am + 64) * 20 + ac * 4] = t1;
            *(uint4*)&Bs[nxt][bk * 72 + bc * 4] = tw;
            __syncthreads();
        }
    }

    const int r0 = bm + warp * 16 + grp;
    #pragma unroll
    for (int j = 0; j < 8; j++) {
        int n = bn + j * 8 + 2 * qd;
        float b0 = bias[n], b1 = bias[n + 1];
        float o00 = (C[j][0] + b0) * scale, o01 = (C[j][1] + b1) * scale;
        float o10 = (C[j][2] + b0) * scale, o11 = (C[j][3] + b1) * scale;
        if (SPLIT) {
            // tf32-round at store so attention can cp.async raw bits
            float2 o0 = { __uint_as_float(f2tf32(o00)), __uint_as_float(f2tf32(o01)) };
            float2 o1 = { __uint_as_float(f2tf32(o10)), __uint_as_float(f2tf32(o11)) };
            int hh = n >> 6, dh = n & 63;
            int ba = r0 >> 11, s0 = r0 & 2047;
            *(float2*)(out + (((size_t)(ba * NH + hh) * NQ + s0) * 64 + dh)) = o0;
            int r1 = r0 + 8, ba1 = r1 >> 11, s1 = r1 & 2047;
            *(float2*)(out + (((size_t)(ba1 * NH + hh) * NQ + s1) * 64 + dh)) = o1;
        } else {
            float2 o0 = { o00, o01 }, o1 = { o10, o11 };
            *(float2*)(out + (size_t)r0 * 512 + n) = o0;
            *(float2*)(out + (size_t)(r0 + 8) * 512 + n) = o1;
        }
    }
}

__global__ __launch_bounds__(256) void gemm_qkv_kernel(
    const float* __restrict__ qs, const float* __restrict__ ks, const float* __restrict__ vs,
    const float* __restrict__ Wq, const float* __restrict__ Wk, const float* __restrict__ Wv,
    const float* __restrict__ bq, const float* __restrict__ bk, const float* __restrict__ bv,
    float* __restrict__ gq, float* __restrict__ gk, float* __restrict__ gv)
{
    const int z = blockIdx.z;
    const float* X = (z == 0) ? qs : (z == 1) ? ks : vs;
    const float* W = (z == 0) ? Wq : (z == 1) ? Wk : Wv;
    const float* B = (z == 0) ? bq : (z == 1) ? bk : bv;
    float* O = (z == 0) ? gq : (z == 1) ? gk : gv;
    gemm_body<1>(X, W, B, O, (z == 0) ? 0.125f : 1.0f);
}

__global__ __launch_bounds__(256) void gemm_o_kernel(
    const float* __restrict__ X, const float* __restrict__ W,
    const float* __restrict__ bias, float* __restrict__ out)
{
    gemm_body<0>(X, W, bias, out, 1.0f);
}

// ---------------------------------------------------------------------------
// Flash attention, tf32 mma; bias via precomputed t = d*LUT_K + per-head LUT.
// Grid (Q/128, H, B), 256 threads (8 warps), warp = 16 q-rows x 64 keys.
// K/V/Q fills via cp.async of pre-rounded tf32 bits.
// ---------------------------------------------------------------------------
#define ATTN_SMEM_BYTES ((128*68 + 64*68 + 64*72) * 4 + NLUT * 8)

__global__ __launch_bounds__(256, 2) void attn_kernel(
    const float* __restrict__ pa, const float* __restrict__ pb,
    const float* __restrict__ pc, const int* __restrict__ vlens)
{
    extern __shared__ float smem[];
    float*  Qs  = smem;                      // [128][68]
    float*  Ks  = Qs + 128 * 68;             // [64][68]
    float*  Vs  = Ks + 64 * 68;              // [64][72]
    float2* lut = (float2*)(Vs + 64 * 72);   // [NLUT] (base_t, slope_t)

    const int tid  = threadIdx.x;
    const int warp = tid >> 5, lane = tid & 31;
    const int grp  = lane >> 2, qd = lane & 3;
    const int q0 = blockIdx.x * 128;
    const int h  = blockIdx.y;
    const int b  = blockIdx.z;
    const int vlen = vlens[b];

    // ---- Q tile via cp.async (overlaps LUT build) ----
    const float* qbase = g_q + ((size_t)(b * NH + h) * NQ + q0) * 64;
    #pragma unroll
    for (int it = 0; it < 8; it++) {
        int i = tid + it * 256;                // 2048 float4-slots / 256 thr
        int r = i >> 4, c = i & 15;
        cp16(&Qs[r * 68 + c * 4], qbase + (size_t)r * 64 + c * 4);
    }

    // ---- per-head bias LUT in t-units: bias(t) = base + slope*t ----
    {
        float ah[NF], nbf[NF], cf[NF];
        #pragma unroll
        for (int f = 0; f < NF; f++) {
            ah[f]  = pa[h * NF + f];
            nbf[f] = -fabsf(pb[h * NF + f]) * LOG2E;
            cf[f]  = pc[h * NF + f];
        }
        for (int i = tid; i < NLUT; i += 256) {
            float d0 = i * LUT_H, d1 = d0 + LUT_H;
            float v0 = 0.f, v1 = 0.f;
            #pragma unroll
            for (int f = 0; f < NF; f++) {
                float t0 = d0 - cf[f], t1 = d1 - cf[f];
                v0 = fmaf(ah[f], ex2f(nbf[f] * t0 * t0), v0);
                v1 = fmaf(ah[f], ex2f(nbf[f] * t1 * t1), v1);
            }
            float slope = v1 - v0;              // per 1.0 in t
            lut[i] = make_float2(fmaf(-slope, (float)i, v0), slope);
        }
    }

    const int rr = warp * 16 + grp;             // first owned q-row
    const float* trow0 = g_t + ((size_t)b * NQ + q0 + rr) * NKK;
    const float* trow1 = trow0 + (size_t)8 * NKK;

    float O[8][4] = {};
    float m0 = -CUDART_INF_F, m1 = -CUDART_INF_F, l0 = 0.f, l1 = 0.f;

    const int ntiles = (vlen + 63) >> 6;
    const float* kptr = g_k + (size_t)(b * NH + h) * NKK * 64;
    const float* vptr = g_v + (size_t)(b * NH + h) * NKK * 64;

    for (int t = 0; t < ntiles; t++) {
        const int kb = t * 64;
        __syncthreads();   // prior compute done (iter0: lut written)
        #pragma unroll
        for (int it = 0; it < 4; it++) {
            int i = tid + it * 256;             // 1024 float4-slots each
            int key = i >> 4, c = i & 15;
            cp16(&Ks[key * 68 + c * 4], kptr + (size_t)(kb + key) * 64 + c * 4);
            cp16(&Vs[key * 72 + c * 4], vptr + (size_t)(kb + key) * 64 + c * 4);
        }
        cp_wait_all();
        __syncthreads();

        // ---- scores: S = Q @ K^T ----
        float S[8][4] = {};
        #pragma unroll
        for (int k8 = 0; k8 < 8; k8++) {
            int kc = k8 * 8 + qd;
            uint32_t a0 = __float_as_uint(Qs[(rr    ) * 68 + kc    ]);
            uint32_t a1 = __float_as_uint(Qs[(rr + 8) * 68 + kc    ]);
            uint32_t a2 = __float_as_uint(Qs[(rr    ) * 68 + kc + 4]);
            uint32_t a3 = __float_as_uint(Qs[(rr + 8) * 68 + kc + 4]);
            #pragma unroll
            for (int j = 0; j < 8; j++) {
                uint32_t b0 = __float_as_uint(Ks[(j*8 + grp) * 68 + kc    ]);
                uint32_t b1 = __float_as_uint(Ks[(j*8 + grp) * 68 + kc + 4]);
                mma_tf32(S[j], a0, a1, a2, a3, b0, b1);
            }
        }

        // ---- bias via precomputed t + LUT; mask ----
        const bool partial = (kb + 64 > vlen);
        #pragma unroll
        for (int j = 0; j < 8; j++) {
            int cl = j * 8 + 2 * qd;
            float2 t0 = *(const float2*)(trow0 + kb + cl);
            float2 t1 = *(const float2*)(trow1 + kb + cl);
            int i0 = min((int)t0.x, NLUT - 1);
            int i1 = min((int)t0.y, NLUT - 1);
            int i2 = min((int)t1.x, NLUT - 1);
            int i3 = min((int)t1.y, NLUT - 1);
            float2 e0 = lut[i0], e1 = lut[i1], e2 = lut[i2], e3 = lut[i3];
            S[j][0] += fmaf(e0.y, t0.x, e0.x);
            S[j][1] += fmaf(e1.y, t0.y, e1.x);
            S[j][2] += fmaf(e2.y, t1.x, e2.x);
            S[j][3] += fmaf(e3.y, t1.y, e3.x);
            if (partial) {
                if (kb + cl     >= vlen) { S[j][0] = -CUDART_INF_F; S[j][2] = -CUDART_INF_F; }
                if (kb + cl + 1 >= vlen) { S[j][1] = -CUDART_INF_F; S[j][3] = -CUDART_INF_F; }
            }
        }

        // ---- online softmax ----
        float tm0 = -CUDART_INF_F, tm1 = -CUDART_INF_F;
        #pragma unroll
        for (int j = 0; j < 8; j++) {
            tm0 = fmaxf(tm0, fmaxf(S[j][0], S[j][1]));
            tm1 = fmaxf(tm1, fmaxf(S[j][2], S[j][3]));
        }
        tm0 = fmaxf(tm0, __shfl_xor_sync(0xffffffffu, tm0, 1));
        tm0 = fmaxf(tm0, __shfl_xor_sync(0xffffffffu, tm0, 2));
        tm1 = fmaxf(tm1, __shfl_xor_sync(0xffffffffu, tm1, 1));
        tm1 = fmaxf(tm1, __shfl_xor_sync(0xffffffffu, tm1, 2));
        float mn0 = fmaxf(m0, tm0), mn1 = fmaxf(m1, tm1);
        float sc0 = ex2f((m0 - mn0) * LOG2E);
        float sc1 = ex2f((m1 - mn1) * LOG2E);
        m0 = mn0; m1 = mn1;

        // exp + C->A fragment relayout via intra-quad shuffles
        float rs0 = 0.f, rs1 = 0.f;
        const int s1 = qd >> 1, s2 = s1 + 2;
        const bool odd = (qd & 1);
        #pragma unroll
        for (int j = 0; j < 8; j++) {
            float p0 = ex2f((S[j][0] - mn0) * LOG2E);
            float p1 = ex2f((S[j][1] - mn0) * LOG2E);
            float p2 = ex2f((S[j][2] - mn1) * LOG2E);
            float p3 = ex2f((S[j][3] - mn1) * LOG2E);
            rs0 += p0 + p1;
            rs1 += p2 + p3;
            float u0 = __shfl_sync(0xffffffffu, p0, s1, 4);
            float u1 = __shfl_sync(0xffffffffu, p1, s1, 4);
            float w0 = __shfl_sync(0xffffffffu, p0, s2, 4);
            float w1 = __shfl_sync(0xffffffffu, p1, s2, 4);
            float t0 = __shfl_sync(0xffffffffu, p2, s1, 4);
            float t1 = __shfl_sync(0xffffffffu, p3, s1, 4);
            float v0 = __shfl_sync(0xffffffffu, p2, s2, 4);
            float v1 = __shfl_sync(0xffffffffu, p3, s2, 4);
            S[j][0] = __uint_as_float(f2tf32(odd ? u1 : u0));
            S[j][1] = __uint_as_float(f2tf32(odd ? t1 : t0));
            S[j][2] = __uint_as_float(f2tf32(odd ? w1 : w0));
            S[j][3] = __uint_as_float(f2tf32(odd ? v1 : v0));
        }
        rs0 += __shfl_xor_sync(0xffffffffu, rs0, 1);
        rs0 += __shfl_xor_sync(0xffffffffu, rs0, 2);
        rs1 += __shfl_xor_sync(0xffffffffu, rs1, 1);
        rs1 += __shfl_xor_sync(0xffffffffu, rs1, 2);
        l0 = l0 * sc0 + rs0;
        l1 = l1 * sc1 + rs1;
        #pragma unroll
        for (int j = 0; j < 8; j++) {
            O[j][0] *= sc0; O[j][1] *= sc0;
            O[j][2] *= sc1; O[j][3] *= sc1;
        }

        // ---- PV ----
        #pragma unroll
        for (int k8 = 0; k8 < 8; k8++) {
            uint32_t a0 = __float_as_uint(S[k8][0]);
            uint32_t a1 = __float_as_uint(S[k8][1]);
            uint32_t a2 = __float_as_uint(S[k8][2]);
            uint32_t a3 = __float_as_uint(S[k8][3]);
            #pragma unroll
            for (int j = 0; j < 8; j++) {
                uint32_t b0 = __float_as_uint(Vs[(k8*8 + qd    ) * 72 + j*8 + grp]);
                uint32_t b1 = __float_as_uint(Vs[(k8*8 + qd + 4) * 72 + j*8 + grp]);
                mma_tf32(O[j], a0, a1, a2, a3, b0, b1);
            }
        }
    }

    // ---- normalize + write context ----
    float li0 = 1.0f / l0, li1 = 1.0f / l1;
    float* obase = g_ctx + ((size_t)(b * NQ + q0 + rr)) * 512 + h * 64;
    #pragma unroll
    for (int j = 0; j < 8; j++) {
        int cl = j * 8 + 2 * qd;
        float2 o0 = { O[j][0] * li0, O[j][1] * li0 };
        float2 o1 = { O[j][2] * li1, O[j][3] * li1 };
        *(float2*)(obase + cl) = o0;
        *(float2*)(obase + (size_t)8 * 512 + cl) = o1;
    }
}

// ---------------------------------------------------------------------------
extern "C" void kernel_launch(void* const* d_in, const int* in_sizes, int n_in,
                              void* d_out, int out_size)
{
    const float* qs    = (const float*)d_in[0];
    const float* ks    = (const float*)d_in[1];
    const float* vs    = (const float*)d_in[2];
    const float* qlocs = (const float*)d_in[3];
    const float* klocs = (const float*)d_in[4];
    const float* Wq    = (const float*)d_in[5];
    const float* bq    = (const float*)d_in[6];
    const float* Wk    = (const float*)d_in[7];
    const float* bk    = (const float*)d_in[8];
    const float* Wv    = (const float*)d_in[9];
    const float* bv    = (const float*)d_in[10];
    const float* Wo    = (const float*)d_in[11];
    const float* bo    = (const float*)d_in[12];
    const float* pa    = (const float*)d_in[13];
    const float* pb    = (const float*)d_in[14];
    const float* pc    = (const float*)d_in[15];
    const int*   vlens = (const int*)d_in[16];
    float* out = (float*)d_out;

    float *gq, *gk, *gv, *gctx;
    cudaGetSymbolAddress((void**)&gq,   g_q);
    cudaGetSymbolAddress((void**)&gk,   g_k);
    cudaGetSymbolAddress((void**)&gv,   g_v);
    cudaGetSymbolAddress((void**)&gctx, g_ctx);

    cudaFuncSetAttribute(attn_kernel,
                         cudaFuncAttributeMaxDynamicSharedMemorySize,
                         ATTN_SMEM_BYTES);

    dist_kernel<<<dim3(NQ, NB), 256>>>(qlocs, klocs);

    gemm_qkv_kernel<<<dim3(8, 32, 3), 256>>>(qs, ks, vs, Wq, Wk, Wv,
                                             bq, bk, bv, gq, gk, gv);

    attn_kernel<<<dim3(NQ / 128, NH, NB), 256, ATTN_SMEM_BYTES>>>(
        pa, pb, pc, vlens);

    gemm_o_kernel<<<dim3(8, 32), 256>>>(gctx, Wo, bo, out);
}